// round 4
// baseline (speedup 1.0000x reference)
#include <cuda_runtime.h>
#include <cuda_bf16.h>

// Hawkes log-likelihood, N=16, T=2048. O(T) affine-recurrence reformulation:
//   A[i] = g[i]*(A[i-1]+1),  g[i] = exp(-beta*(t_i - t_{i-1})),  A[0]=0.
// R4: post-barrier critical path minimized:
//   - replay linearized: A_j = P_j*Ain + Q_j, mask/alpha/mu folded pre-barrier
//     so post-scan work is 8 parallel FMAs + product tree + one log
//   - S/Ms computed and warp-reduced pre-barrier; final S/Ms reduce overlaps
//     the redundant cross-warp scan in warp 0
//   - chunk P from prefix products (one fewer exp); __fdividef tail

#define TT 2048
#define BLK 256
#define CHUNK 8
#define NW (BLK / 32)   // 8 warps

__global__ __launch_bounds__(BLK)
void hawkes_kernel(const float* __restrict__ et,
                   const float* __restrict__ mask,
                   const float* __restrict__ t0p,
                   const float* __restrict__ t1p,
                   const float* __restrict__ mup,
                   const float* __restrict__ alphap,
                   const float* __restrict__ betap,
                   float* __restrict__ out)
{
    const int n    = blockIdx.x;
    const int k    = threadIdx.x;
    const int lane = k & 31;
    const int wid  = k >> 5;

    // ---- issue all loads up front (params gate the exps) ----
    const float mur = __ldg(mup);
    const float alr = __ldg(alphap);
    const float ber = __ldg(betap);

    const float* t = et   + n * TT;
    const float* m = mask + n * TT;
    const int base = k * CHUNK;

    const float4 ta = __ldg((const float4*)(t + base));
    const float4 tb = __ldg((const float4*)(t + base + 4));
    const float4 ma = __ldg((const float4*)(m + base));
    const float4 mb = __ldg((const float4*)(m + base + 4));
    const float tm1 = (base == 0) ? 0.0f : __ldg(t + base - 1);
    const float t0  = __ldg(t0p + n);
    const float t1  = __ldg(t1p + n);

    // softplus (fast MUFU; tolerance 1e-3, we're at ~5e-7)
    const float mu    = __logf(1.0f + __expf(mur));
    const float alpha = __logf(1.0f + __expf(alr));
    const float beta  = __logf(1.0f + __expf(ber));

    float tv[CHUNK] = {ta.x, ta.y, ta.z, ta.w, tb.x, tb.y, tb.z, tb.w};
    float mv[CHUNK] = {ma.x, ma.y, ma.z, ma.w, mb.x, mb.y, mb.z, mb.w};

    // ---- local pass: g, chunk-local prefix (P_j, Q_j) ----
    float g[CHUNK], Pj[CHUNK], Qj[CHUNK];
    float tprev = tm1;
    float A  = 0.0f;   // local Q
    float Pp = 1.0f;   // local prefix product of g
    #pragma unroll
    for (int j = 0; j < CHUNK; ++j) {
        float gj = __expf(-beta * (tv[j] - tprev));
        if (base + j == 0) gj = 0.0f;
        g[j] = gj;
        tprev = tv[j];
        A  = fmaf(gj, A, gj);          // g*(A+1)
        Pp *= gj;
        Pj[j] = Pp;
        Qj[j] = A;
    }
    float p = Pj[CHUNK - 1];           // chunk transfer: x -> p*x + q
    float q = A;

    // ---- compensator terms (scan-independent; overlaps the scan) ----
    float w  = __expf(-beta * (t1 - tv[CHUNK - 1]));
    float S  = mv[CHUNK - 1] * w;
    float Ms = mv[CHUNK - 1];
    #pragma unroll
    for (int j = CHUNK - 2; j >= 0; --j) {
        w *= g[j + 1];                 // -> exp(-beta*(t1 - t_j))
        S  = fmaf(mv[j], w, S);
        Ms += mv[j];
    }

    // ---- intra-warp inclusive affine scan (5 shfl steps) ----
    #pragma unroll
    for (int d = 1; d < 32; d <<= 1) {
        float pe = __shfl_up_sync(0xffffffffu, p, d);
        float qe = __shfl_up_sync(0xffffffffu, q, d);
        if (lane >= d) {
            q = fmaf(p, qe, q);
            p = p * pe;
        }
    }
    // thread-exclusive prefix (pre-barrier)
    float pie = __shfl_up_sync(0xffffffffu, p, 1);
    float qie = __shfl_up_sync(0xffffffffu, q, 1);
    if (lane == 0) { pie = 1.0f; qie = 0.0f; }

    // ---- warp-reduce S, Ms (pre-barrier; fills shfl latency shadows) ----
    #pragma unroll
    for (int d = 16; d > 0; d >>= 1) {
        S  += __shfl_xor_sync(0xffffffffu, S,  d);
        Ms += __shfl_xor_sync(0xffffffffu, Ms, d);
    }

    // ---- fold mask/alpha/mu into per-element affine coeffs (pre-barrier) ----
    // term_j = m*lamb + (1-m),  lamb = alpha*(P_j*Ain + Q_j) + mu + 1e-8
    //        = fma(u_j, Ain, v_j)
    float uj[CHUNK], vj[CHUNK];
    const float mueps = mu + 1e-8f;
    #pragma unroll
    for (int j = 0; j < CHUNK; ++j) {
        float maP = mv[j] * alpha;
        uj[j] = maP * Pj[j];
        vj[j] = fmaf(mv[j], fmaf(alpha, Qj[j], mueps) - 1.0f, 1.0f);
    }

    __shared__ float sWP[NW], sWQ[NW];
    __shared__ float sAcc[NW], sS[NW], sMs[NW];
    if (lane == 31) { sWP[wid] = p; sWQ[wid] = q; }
    if (lane == 0)  { sS[wid] = S;  sMs[wid] = Ms; }
    __syncthreads();                                   // barrier 1

    // ---- cross-warp: every warp redundantly scans the 8 aggregates ----
    float wp = (lane < NW) ? sWP[lane] : 1.0f;
    float wq = (lane < NW) ? sWQ[lane] : 0.0f;
    #pragma unroll
    for (int d = 1; d < NW; d <<= 1) {
        float pe = __shfl_up_sync(0xffffffffu, wp, d);
        float qe = __shfl_up_sync(0xffffffffu, wq, d);
        if (lane >= d) {
            wq = fmaf(wp, qe, wq);
            wp = wp * pe;
        }
    }
    float qw = __shfl_sync(0xffffffffu, wq, (wid == 0) ? 0 : (wid - 1));
    if (wid == 0) qw = 0.0f;
    const float Ain = fmaf(pie, qw, qie);

    // warp 0: final S/Ms reduce, concurrent with the scan chain above
    float s2 = 0.0f, m2 = 0.0f;
    if (wid == 0 && lane < NW) {
        s2 = sS[lane]; m2 = sMs[lane];
        #pragma unroll
        for (int d = NW / 2; d > 0; d >>= 1) {
            s2 += __shfl_xor_sync(0xffu, s2, d);
            m2 += __shfl_xor_sync(0xffu, m2, d);
        }
    }

    // ---- replay: 8 parallel FMAs + product tree + one log ----
    float tm[CHUNK];
    #pragma unroll
    for (int j = 0; j < CHUNK; ++j)
        tm[j] = fmaf(uj[j], Ain, vj[j]);
    float p01 = tm[0] * tm[1], p23 = tm[2] * tm[3];
    float p45 = tm[4] * tm[5], p67 = tm[6] * tm[7];
    float acc = __logf((p01 * p23) * (p45 * p67));

    // ---- reduce acc ----
    #pragma unroll
    for (int d = 16; d > 0; d >>= 1)
        acc += __shfl_xor_sync(0xffffffffu, acc, d);
    if (lane == 0) sAcc[wid] = acc;
    __syncthreads();                                   // barrier 2
    if (wid == 0 && lane < NW) {
        float a2 = sAcc[lane];
        #pragma unroll
        for (int d = NW / 2; d > 0; d >>= 1)
            a2 += __shfl_xor_sync(0xffu, a2, d);
        if (lane == 0) {
            float comp = (t1 - t0) * mu - __fdividef(alpha, beta) * (s2 - m2);
            out[n] = a2 - comp;
        }
    }
}

extern "C" void kernel_launch(void* const* d_in, const int* in_sizes, int n_in,
                              void* d_out, int out_size)
{
    const float* event_times = (const float*)d_in[0];
    const float* input_mask  = (const float*)d_in[1];
    const float* t0          = (const float*)d_in[2];
    const float* t1          = (const float*)d_in[3];
    const float* mu          = (const float*)d_in[4];
    const float* alpha       = (const float*)d_in[5];
    const float* beta        = (const float*)d_in[6];
    float* out = (float*)d_out;

    const int N = in_sizes[2];  // t0 has N elements

    hawkes_kernel<<<N, BLK>>>(event_times, input_mask, t0, t1, mu, alpha, beta, out);
}